// round 10
// baseline (speedup 1.0000x reference)
#include <cuda_runtime.h>

// SortPool2D: x (16,224,224,256) fp32 NHWC -> out (16,112,112,256)
// Sort 2x2 spatial values ascending, dot with softmax(pool_weights[4]).
// HBM-bound stream (822MB in + 205MB out, each byte touched once).
// Persistent grid-stride kernel: 148*8 CTAs loop over outputs, eliminating
// CTA spawn/retire churn and wave-transition bubbles of the 50k-CTA launch.

#define B_DIM    16
#define H_IN     224
#define W_IN     224
#define C_DIM    256
#define H_OUT    (H_IN / 2)     // 112
#define W_OUT    (W_IN / 2)     // 112
#define C4       (C_DIM / 4)    // 64 float4 per pixel
#define IN_ROW4  (W_IN * C4)    // 14336 float4 per input row
#define TOTAL4   (B_DIM * H_OUT * W_OUT * C4)  // 12,845,056 output float4

#define NTHREADS 256
#define NCTAS    (148 * 8)      // 1184 persistent CTAs

__device__ __forceinline__ float sort4_dot(float a, float b, float c, float d,
                                           float w0, float w1, float w2, float w3) {
    float lo0 = fminf(a, b), hi0 = fmaxf(a, b);
    float lo1 = fminf(c, d), hi1 = fmaxf(c, d);
    float s0  = fminf(lo0, lo1);
    float t0  = fmaxf(lo0, lo1);
    float t1  = fminf(hi0, hi1);
    float s3  = fmaxf(hi0, hi1);
    float s1  = fminf(t0, t1);
    float s2  = fmaxf(t0, t1);
    return fmaf(s0, w0, fmaf(s1, w1, fmaf(s2, w2, s3 * w3)));
}

__global__ void __launch_bounds__(NTHREADS)
sortpool2d_kernel(const float4* __restrict__ x,
                  const float*  __restrict__ pw,
                  float4*       __restrict__ out) {
    __shared__ float w[4];
    if (threadIdx.x == 0) {
        float a0 = pw[0], a1 = pw[1], a2 = pw[2], a3 = pw[3];
        float m  = fmaxf(fmaxf(a0, a1), fmaxf(a2, a3));
        float e0 = __expf(a0 - m), e1 = __expf(a1 - m);
        float e2 = __expf(a2 - m), e3 = __expf(a3 - m);
        float inv = 1.0f / (e0 + e1 + e2 + e3);
        w[0] = e0 * inv; w[1] = e1 * inv; w[2] = e2 * inv; w[3] = e3 * inv;
    }
    __syncthreads();
    float w0 = w[0], w1 = w[1], w2 = w[2], w3 = w[3];

    const unsigned stride = NCTAS * NTHREADS;   // 303,104

    #pragma unroll 2
    for (unsigned o = blockIdx.x * NTHREADS + threadIdx.x; o < TOTAL4; o += stride) {
        // Decompose output float4 index: (b, h, wo, c4)
        unsigned c4 = o & (C4 - 1);
        unsigned t  = o >> 6;                 // C4 == 64
        unsigned wo = t % W_OUT;
        unsigned t2 = t / W_OUT;
        unsigned h  = t2 % H_OUT;
        unsigned b  = t2 / H_OUT;

        long base = ((long)(b * H_IN + 2u * h) * W_IN + 2u * wo) * C4 + c4;

        float4 v00 = x[base];
        float4 v01 = x[base + C4];
        float4 v10 = x[base + IN_ROW4];
        float4 v11 = x[base + IN_ROW4 + C4];

        float4 r;
        r.x = sort4_dot(v00.x, v01.x, v10.x, v11.x, w0, w1, w2, w3);
        r.y = sort4_dot(v00.y, v01.y, v10.y, v11.y, w0, w1, w2, w3);
        r.z = sort4_dot(v00.z, v01.z, v10.z, v11.z, w0, w1, w2, w3);
        r.w = sort4_dot(v00.w, v01.w, v10.w, v11.w, w0, w1, w2, w3);

        out[o] = r;
    }
}

extern "C" void kernel_launch(void* const* d_in, const int* in_sizes, int n_in,
                              void* d_out, int out_size) {
    const float4* x  = (const float4*)d_in[0];
    const float*  pw = (const float*)d_in[1];
    float4*       o  = (float4*)d_out;

    sortpool2d_kernel<<<NCTAS, NTHREADS>>>(x, pw, o);
}

// round 12
// speedup vs baseline: 1.1017x; 1.1017x over previous
#include <cuda_runtime.h>

// SortPool2D: x (16,224,224,256) fp32 NHWC -> out (16,112,112,256)
// Sort 2x2 spatial values ascending, dot with softmax(pool_weights[4]).
// HBM-bound stream (822MB in + 205MB out). Massive-grid one-output-per-thread
// shape measured fastest (144.3us, DRAM=89.3%); this build trims the last
// non-memory work: no bounds branch (exact grid), all-32-bit index math.

#define B_DIM    16
#define H_IN     224
#define W_IN     224
#define C_DIM    256
#define H_OUT    (H_IN / 2)     // 112
#define W_OUT    (W_IN / 2)     // 112
#define C4       (C_DIM / 4)    // 64 float4 per pixel
#define IN_ROW4  (W_IN * C4)    // 14336 float4 per input row
#define TOTAL4   (B_DIM * H_OUT * W_OUT * C4)  // 12,845,056 = 50176 * 256

__device__ __forceinline__ float sort4_dot(float a, float b, float c, float d,
                                           float w0, float w1, float w2, float w3) {
    float lo0 = fminf(a, b), hi0 = fmaxf(a, b);
    float lo1 = fminf(c, d), hi1 = fmaxf(c, d);
    float s0  = fminf(lo0, lo1);   // smallest
    float t0  = fmaxf(lo0, lo1);
    float t1  = fminf(hi0, hi1);
    float s3  = fmaxf(hi0, hi1);   // largest
    float s1  = fminf(t0, t1);
    float s2  = fmaxf(t0, t1);
    return fmaf(s0, w0, fmaf(s1, w1, fmaf(s2, w2, s3 * w3)));
}

__global__ void __launch_bounds__(256)
sortpool2d_kernel(const float4* __restrict__ x,
                  const float*  __restrict__ pw,
                  float4*       __restrict__ out) {
    __shared__ float w[4];
    if (threadIdx.x == 0) {
        float a0 = pw[0], a1 = pw[1], a2 = pw[2], a3 = pw[3];
        float m  = fmaxf(fmaxf(a0, a1), fmaxf(a2, a3));
        float e0 = __expf(a0 - m), e1 = __expf(a1 - m);
        float e2 = __expf(a2 - m), e3 = __expf(a3 - m);
        float inv = 1.0f / (e0 + e1 + e2 + e3);
        w[0] = e0 * inv; w[1] = e1 * inv; w[2] = e2 * inv; w[3] = e3 * inv;
    }
    __syncthreads();
    float w0 = w[0], w1 = w[1], w2 = w[2], w3 = w[3];

    // Exact grid: TOTAL4 == gridDim.x * blockDim.x, no bounds check needed.
    unsigned o = blockIdx.x * 256u + threadIdx.x;

    // Decompose output float4 index: (b, h, wo, c4). All 32-bit.
    unsigned c4 = o & (C4 - 1);
    unsigned t  = o >> 6;                 // C4 == 64
    unsigned wo = t % W_OUT;
    unsigned t2 = t / W_OUT;
    unsigned h  = t2 % H_OUT;
    unsigned b  = t2 / H_OUT;

    // Input base in float4 units; max 51,380,223 < 2^31 so unsigned is safe.
    unsigned base = ((b * H_IN + 2u * h) * W_IN + 2u * wo) * C4 + c4;

    float4 v00 = x[base];
    float4 v01 = x[base + C4];
    float4 v10 = x[base + IN_ROW4];
    float4 v11 = x[base + IN_ROW4 + C4];

    float4 r;
    r.x = sort4_dot(v00.x, v01.x, v10.x, v11.x, w0, w1, w2, w3);
    r.y = sort4_dot(v00.y, v01.y, v10.y, v11.y, w0, w1, w2, w3);
    r.z = sort4_dot(v00.z, v01.z, v10.z, v11.z, w0, w1, w2, w3);
    r.w = sort4_dot(v00.w, v01.w, v10.w, v11.w, w0, w1, w2, w3);

    out[o] = r;
}

extern "C" void kernel_launch(void* const* d_in, const int* in_sizes, int n_in,
                              void* d_out, int out_size) {
    const float4* x  = (const float4*)d_in[0];
    const float*  pw = (const float*)d_in[1];
    float4*       o  = (float4*)d_out;

    sortpool2d_kernel<<<TOTAL4 / 256, 256>>>(x, pw, o);
}